// round 12
// baseline (speedup 1.0000x reference)
#include <cuda_runtime.h>
#include <cstdint>

// Per-row top-k (k=64) of x[16384, 8192] fp32, scattered back densely.
// R12: pure front-batched load phase (no work between the LDG.128s -> max
// MLP), then register-side compaction of f > 2.0 (~186/row). Fine 128-bin
// histogram over candidates only, warp suffix-scan bin select, rank select
// over the ~3 bin members. TPB=512/VPT=4 cuts regs -> 48 warps/SM.
// Widening cascade + overflow fallback keep it exact for ANY input.

#define TPB   512
#define COLS  8192
#define VPT   4            // float4 per thread
#define EPT   16           // elements per thread
#define NBIN  128          // fine bins over [T0, T0+2)
#define CAND2 512          // side buffer for selected-bin members

#define T0    2.0f
#define T1    1.0f

// Monotone fine bucket: clamp(floor((f-T0)*64), 0, 127). NaN -> 0.
__device__ __forceinline__ int cbucket(float f) {
    int b = __float2int_rd((f - T0) * 64.0f);
    return min(max(b, 0), NBIN - 1);
}

__global__ void __launch_bounds__(TPB, 3)
topk_scatter_kernel(const float* __restrict__ x,
                    const unsigned int* __restrict__ kp,
                    float* __restrict__ out)
{
    const int row  = blockIdx.x;
    const int t    = threadIdx.x;
    const int lane = t & 31;
    const int w    = t >> 5;

    __shared__ float    buf[COLS];      // candidates (worst case: whole row)
    __shared__ float    cand2[CAND2];   // selected-bin members
    __shared__ uint32_t hist[NBIN];
    __shared__ uint32_t wsum[NBIN / 32];
    __shared__ uint32_t sh_cnt, sh_sel, sh_hi, sh_e2, sh_keep, sh_neq, sh_tc;
    __shared__ float    sh_thr;

    const float4* __restrict__ xr   = reinterpret_cast<const float4*>(x + (size_t)row * COLS);
    float4* __restrict__       orow = reinterpret_cast<float4*>(out + (size_t)row * COLS);

    if (t == 0) { sh_cnt = 0u; sh_e2 = 0u; }
    if (t < NBIN) hist[t] = 0u;
    __syncthreads();

    // ---- Phase A: pure load (front-batched LDG.128, nothing in between) ----
    float val[EPT];
    float4* v4 = reinterpret_cast<float4*>(val);
#pragma unroll
    for (int j = 0; j < VPT; j++)
        v4[j] = __ldg(&xr[t + j * TPB]);

    // ---- Phase B: compact f > T0 from registers (no global latency left) ----
#pragma unroll
    for (int e = 0; e < EPT; e++) {
        float f = val[e];
        if (f > T0) buf[atomicAdd(&sh_cnt, 1u)] = f;
    }

    // k input (defensive parse; expected 64)
    uint32_t K = 64u;
    if (kp) {
        uint32_t raw = __ldg(kp);
        if (raw >= 1u && raw <= (uint32_t)COLS) {
            K = raw;
        } else {
            float f = __uint_as_float(raw);
            if (f >= 1.0f && f <= (float)COLS) K = (uint32_t)f;
        }
    }
    __syncthreads();

    // ---- widening cascade (exact; never taken for N(0,1) rows w/ K=64) ----
    if (sh_cnt < K) {
#pragma unroll
        for (int e = 0; e < EPT; e++) {
            float f = val[e];
            if (f > T1 && !(f > T0)) buf[atomicAdd(&sh_cnt, 1u)] = f;
        }
        __syncthreads();
        if (sh_cnt < K) {
#pragma unroll
            for (int e = 0; e < EPT; e++) {
                float f = val[e];
                if (!(f > T1)) buf[atomicAdd(&sh_cnt, 1u)] = f;
            }
            __syncthreads();
        }
    }

    const uint32_t cnt = sh_cnt;   // >= K guaranteed

    // ---- fine histogram over candidates only (~cnt atomics total) ----
    for (uint32_t i = t; i < cnt; i += TPB)
        atomicAdd(&hist[cbucket(buf[i])], 1u);
    __syncthreads();

    // ---- select bin containing the K-th largest (suffix scan, 4 warps) ----
    uint32_t tot = 0, s = 0;
    if (t < NBIN) {
        tot = hist[t];
        s = tot;
#pragma unroll
        for (int off = 1; off < 32; off <<= 1) {
            uint32_t v = __shfl_down_sync(0xFFFFFFFFu, s, off);
            if (lane + off < 32) s += v;
        }
        if (lane == 0) wsum[w] = s;
    }
    __syncthreads();
    if (t < NBIN) {
        uint32_t S = s;
#pragma unroll
        for (int j = 0; j < NBIN / 32; j++)
            if (j > w) S += wsum[j];
        if (S >= K && (S - tot) < K) {
            sh_sel = (uint32_t)t;
            sh_hi  = S - tot;        // # candidates in bins above
        }
    }
    __syncthreads();

    const int      sel = (int)sh_sel;
    const uint32_t kkw = K - sh_hi;  // rank within selected bin (>=1)

    // ---- compact selected-bin members into small buffer ----
    for (uint32_t i = t; i < cnt; i += TPB) {
        float f = buf[i];
        if (cbucket(f) == sel) {
            uint32_t p = atomicAdd(&sh_e2, 1u);
            if (p < CAND2) cand2[p] = f;
        }
    }
    __syncthreads();

    const uint32_t e2 = sh_e2;

    // ---- exact rank select within the bin ----
    if (e2 <= CAND2) {
        for (uint32_t i = t; i < e2; i += TPB) {
            float fi = cand2[i];
            uint32_t g = 0, eq = 0;
            for (uint32_t j = 0; j < e2; j++) {
                float fj = cand2[j];
                g  += (fj > fi);
                eq += (fj == fi);
            }
            if (g < kkw && g + eq >= kkw) {
                sh_thr  = fi;
                sh_keep = kkw - g;
                sh_neq  = eq;
            }
        }
    } else {
        // pathological bin overflow: rank-select over buf with membership test
        for (uint32_t i = t; i < cnt; i += TPB) {
            float fi = buf[i];
            if (cbucket(fi) != sel) continue;
            uint32_t g = 0, eq = 0;
            for (uint32_t j = 0; j < cnt; j++) {
                float fj = buf[j];
                if (cbucket(fj) != sel) continue;
                g  += (fj > fi);
                eq += (fj == fi);
            }
            if (g < kkw && g + eq >= kkw) {
                sh_thr  = fi;
                sh_keep = kkw - g;
                sh_neq  = eq;
            }
        }
    }
    __syncthreads();

    const float    thresh = sh_thr;
    const uint32_t keep   = sh_keep;
    const uint32_t neq    = sh_neq;

    // ---- tie resolution (exact lowest-index-first; rare path) ----
    int t_idx = COLS - 1;
    if (neq > keep) {
        int lo = 0, hi = COLS - 1;
        while (lo < hi) {
            int mid = (lo + hi) >> 1;
            if (t == 0) sh_tc = 0u;
            __syncthreads();
            uint32_t local = 0;
#pragma unroll
            for (int j = 0; j < VPT; j++) {
                int base = 4 * (t + j * TPB);
#pragma unroll
                for (int c = 0; c < 4; c++) {
                    if (val[4*j + c] == thresh && (base + c) <= mid) local++;
                }
            }
            if (local) atomicAdd(&sh_tc, local);
            __syncthreads();
            if (sh_tc >= keep) hi = mid; else lo = mid + 1;
            __syncthreads();
        }
        t_idx = lo;
    }

    // ---- write output (coalesced STG.128; 1 FSETP+FSEL per element) ----
    if (neq == keep) {
#pragma unroll
        for (int j = 0; j < VPT; j++) {
            float4 o;
            float f0 = val[4*j+0], f1 = val[4*j+1], f2 = val[4*j+2], f3 = val[4*j+3];
            o.x = (f0 >= thresh) ? f0 : 0.0f;
            o.y = (f1 >= thresh) ? f1 : 0.0f;
            o.z = (f2 >= thresh) ? f2 : 0.0f;
            o.w = (f3 >= thresh) ? f3 : 0.0f;
            orow[t + j * TPB] = o;
        }
    } else {
#pragma unroll
        for (int j = 0; j < VPT; j++) {
            const int base = 4 * (t + j * TPB);
            float4 o;
            float f0 = val[4*j+0], f1 = val[4*j+1], f2 = val[4*j+2], f3 = val[4*j+3];
            o.x = (f0 > thresh || (f0 == thresh && (base + 0) <= t_idx)) ? f0 : 0.0f;
            o.y = (f1 > thresh || (f1 == thresh && (base + 1) <= t_idx)) ? f1 : 0.0f;
            o.z = (f2 > thresh || (f2 == thresh && (base + 2) <= t_idx)) ? f2 : 0.0f;
            o.w = (f3 > thresh || (f3 == thresh && (base + 3) <= t_idx)) ? f3 : 0.0f;
            orow[t + j * TPB] = o;
        }
    }
}

extern "C" void kernel_launch(void* const* d_in, const int* in_sizes, int n_in,
                              void* d_out, int out_size)
{
    const float* x = (const float*)d_in[0];
    const unsigned int* kp = (n_in >= 2) ? (const unsigned int*)d_in[1] : nullptr;

    int rows = out_size / COLS;   // 16384
    topk_scatter_kernel<<<rows, TPB>>>(x, kp, (float*)d_out);
}

// round 13
// speedup vs baseline: 1.0465x; 1.0465x over previous
#include <cuda_runtime.h>
#include <cstdint>

// Per-row top-k (k=64) of x[16384, 8192] fp32, scattered back densely.
// R13: TPB=256 (4 CTAs/SM, the config of every winning round) with R12's
// phase split: pure front-batched load (8x LDG.128, nothing interleaved),
// register-side compaction of f > 2.0 (~186/row), fine 128-bin histogram
// over candidates only, warp suffix-scan bin select, exact rank select over
// the ~3 bin members. Widening cascade + overflow fallback keep it exact
// for ANY input; exact lowest-index tie handling.

#define TPB   256
#define COLS  8192
#define VPT   8            // float4 per thread
#define EPT   32           // elements per thread
#define NBIN  128          // fine bins over [T0, T0+2)
#define CAND2 512          // side buffer for selected-bin members

#define T0    2.0f
#define T1    1.0f

// Monotone fine bucket: clamp(floor((f-T0)*64), 0, 127). NaN -> 0.
__device__ __forceinline__ int cbucket(float f) {
    int b = __float2int_rd((f - T0) * 64.0f);
    return min(max(b, 0), NBIN - 1);
}

__global__ void __launch_bounds__(TPB, 4)
topk_scatter_kernel(const float* __restrict__ x,
                    const unsigned int* __restrict__ kp,
                    float* __restrict__ out)
{
    const int row  = blockIdx.x;
    const int t    = threadIdx.x;
    const int lane = t & 31;
    const int w    = t >> 5;

    __shared__ float    buf[COLS];      // candidates (worst case: whole row)
    __shared__ float    cand2[CAND2];   // selected-bin members
    __shared__ uint32_t hist[NBIN];
    __shared__ uint32_t wsum[NBIN / 32];
    __shared__ uint32_t sh_cnt, sh_sel, sh_hi, sh_e2, sh_keep, sh_neq, sh_tc;
    __shared__ float    sh_thr;

    const float4* __restrict__ xr   = reinterpret_cast<const float4*>(x + (size_t)row * COLS);
    float4* __restrict__       orow = reinterpret_cast<float4*>(out + (size_t)row * COLS);

    if (t == 0) { sh_cnt = 0u; sh_e2 = 0u; }
    if (t < NBIN) hist[t] = 0u;
    __syncthreads();

    // ---- Phase A: pure load (front-batched LDG.128, nothing in between) ----
    float val[EPT];
    float4* v4 = reinterpret_cast<float4*>(val);
#pragma unroll
    for (int j = 0; j < VPT; j++)
        v4[j] = __ldg(&xr[t + j * TPB]);

    // ---- Phase B: compact f > T0 from registers ----
#pragma unroll
    for (int e = 0; e < EPT; e++) {
        float f = val[e];
        if (f > T0) buf[atomicAdd(&sh_cnt, 1u)] = f;
    }

    // k input (defensive parse; expected 64)
    uint32_t K = 64u;
    if (kp) {
        uint32_t raw = __ldg(kp);
        if (raw >= 1u && raw <= (uint32_t)COLS) {
            K = raw;
        } else {
            float f = __uint_as_float(raw);
            if (f >= 1.0f && f <= (float)COLS) K = (uint32_t)f;
        }
    }
    __syncthreads();

    // ---- widening cascade (exact; never taken for N(0,1) rows w/ K=64) ----
    if (sh_cnt < K) {
#pragma unroll
        for (int e = 0; e < EPT; e++) {
            float f = val[e];
            if (f > T1 && !(f > T0)) buf[atomicAdd(&sh_cnt, 1u)] = f;
        }
        __syncthreads();
        if (sh_cnt < K) {
#pragma unroll
            for (int e = 0; e < EPT; e++) {
                float f = val[e];
                if (!(f > T1)) buf[atomicAdd(&sh_cnt, 1u)] = f;
            }
            __syncthreads();
        }
    }

    const uint32_t cnt = sh_cnt;   // >= K guaranteed

    // ---- fine histogram over candidates only (~cnt atomics total) ----
    for (uint32_t i = t; i < cnt; i += TPB)
        atomicAdd(&hist[cbucket(buf[i])], 1u);
    __syncthreads();

    // ---- select bin containing the K-th largest (suffix scan, 4 warps) ----
    uint32_t tot = 0, s = 0;
    if (t < NBIN) {
        tot = hist[t];
        s = tot;
#pragma unroll
        for (int off = 1; off < 32; off <<= 1) {
            uint32_t v = __shfl_down_sync(0xFFFFFFFFu, s, off);
            if (lane + off < 32) s += v;
        }
        if (lane == 0) wsum[w] = s;
    }
    __syncthreads();
    if (t < NBIN) {
        uint32_t S = s;
#pragma unroll
        for (int j = 0; j < NBIN / 32; j++)
            if (j > w) S += wsum[j];
        if (S >= K && (S - tot) < K) {
            sh_sel = (uint32_t)t;
            sh_hi  = S - tot;        // # candidates in bins above
        }
    }
    __syncthreads();

    const int      sel = (int)sh_sel;
    const uint32_t kkw = K - sh_hi;  // rank within selected bin (>=1)

    // ---- compact selected-bin members into small buffer ----
    for (uint32_t i = t; i < cnt; i += TPB) {
        float f = buf[i];
        if (cbucket(f) == sel) {
            uint32_t p = atomicAdd(&sh_e2, 1u);
            if (p < CAND2) cand2[p] = f;
        }
    }
    __syncthreads();

    const uint32_t e2 = sh_e2;

    // ---- exact rank select within the bin ----
    if (e2 <= CAND2) {
        for (uint32_t i = t; i < e2; i += TPB) {
            float fi = cand2[i];
            uint32_t g = 0, eq = 0;
            for (uint32_t j = 0; j < e2; j++) {
                float fj = cand2[j];
                g  += (fj > fi);
                eq += (fj == fi);
            }
            if (g < kkw && g + eq >= kkw) {
                sh_thr  = fi;
                sh_keep = kkw - g;
                sh_neq  = eq;
            }
        }
    } else {
        // pathological bin overflow: rank-select over buf with membership test
        for (uint32_t i = t; i < cnt; i += TPB) {
            float fi = buf[i];
            if (cbucket(fi) != sel) continue;
            uint32_t g = 0, eq = 0;
            for (uint32_t j = 0; j < cnt; j++) {
                float fj = buf[j];
                if (cbucket(fj) != sel) continue;
                g  += (fj > fi);
                eq += (fj == fi);
            }
            if (g < kkw && g + eq >= kkw) {
                sh_thr  = fi;
                sh_keep = kkw - g;
                sh_neq  = eq;
            }
        }
    }
    __syncthreads();

    const float    thresh = sh_thr;
    const uint32_t keep   = sh_keep;
    const uint32_t neq    = sh_neq;

    // ---- tie resolution (exact lowest-index-first; rare path) ----
    int t_idx = COLS - 1;
    if (neq > keep) {
        int lo = 0, hi = COLS - 1;
        while (lo < hi) {
            int mid = (lo + hi) >> 1;
            if (t == 0) sh_tc = 0u;
            __syncthreads();
            uint32_t local = 0;
#pragma unroll
            for (int j = 0; j < VPT; j++) {
                int base = 4 * (t + j * TPB);
#pragma unroll
                for (int c = 0; c < 4; c++) {
                    if (val[4*j + c] == thresh && (base + c) <= mid) local++;
                }
            }
            if (local) atomicAdd(&sh_tc, local);
            __syncthreads();
            if (sh_tc >= keep) hi = mid; else lo = mid + 1;
            __syncthreads();
        }
        t_idx = lo;
    }

    // ---- write output (coalesced STG.128; 1 FSETP+FSEL per element) ----
    if (neq == keep) {
#pragma unroll
        for (int j = 0; j < VPT; j++) {
            float4 o;
            float f0 = val[4*j+0], f1 = val[4*j+1], f2 = val[4*j+2], f3 = val[4*j+3];
            o.x = (f0 >= thresh) ? f0 : 0.0f;
            o.y = (f1 >= thresh) ? f1 : 0.0f;
            o.z = (f2 >= thresh) ? f2 : 0.0f;
            o.w = (f3 >= thresh) ? f3 : 0.0f;
            orow[t + j * TPB] = o;
        }
    } else {
#pragma unroll
        for (int j = 0; j < VPT; j++) {
            const int base = 4 * (t + j * TPB);
            float4 o;
            float f0 = val[4*j+0], f1 = val[4*j+1], f2 = val[4*j+2], f3 = val[4*j+3];
            o.x = (f0 > thresh || (f0 == thresh && (base + 0) <= t_idx)) ? f0 : 0.0f;
            o.y = (f1 > thresh || (f1 == thresh && (base + 1) <= t_idx)) ? f1 : 0.0f;
            o.z = (f2 > thresh || (f2 == thresh && (base + 2) <= t_idx)) ? f2 : 0.0f;
            o.w = (f3 > thresh || (f3 == thresh && (base + 3) <= t_idx)) ? f3 : 0.0f;
            orow[t + j * TPB] = o;
        }
    }
}

extern "C" void kernel_launch(void* const* d_in, const int* in_sizes, int n_in,
                              void* d_out, int out_size)
{
    const float* x = (const float*)d_in[0];
    const unsigned int* kp = (n_in >= 2) ? (const unsigned int*)d_in[1] : nullptr;

    int rows = out_size / COLS;   // 16384
    topk_scatter_kernel<<<rows, TPB>>>(x, kp, (float*)d_out);
}